// round 13
// baseline (speedup 1.0000x reference)
#include <cuda_runtime.h>
#include <math.h>
#include <stdint.h>

#define N_LEVELS 16
#define LOG2_HASHMAP_SIZE 19
#define HASH_MASK ((1u << LOG2_HASHMAP_SIZE) - 1u)
#define N_POINTS 1048576
#define PRIME_Y 2654435761u
#define PRIME_Z 805459861u
#define N_BINS 262144         // 64^3 spatial bins, Morton-ordered

struct Res16 { float r[16]; };

// Scratch (no cudaMalloc allowed)
__device__ float4       g_xs4[N_POINTS];      // sorted points + orig idx in .w
__device__ unsigned int g_hist[N_BINS + 1];   // counts->offsets; [N_BINS] = ticket

__device__ __forceinline__ uint32_t part1by2(uint32_t v) {
    v &= 0x3FFu;
    v = (v * 0x00010001u) & 0xFF0000FFu;
    v = (v * 0x00000101u) & 0x0F00F00Fu;
    v = (v * 0x00000011u) & 0xC30C30C3u;
    v = (v * 0x00000005u) & 0x49249249u;
    return v;
}

// Morton key over 64^3: consecutive bins tile space as nested cubes, so 32
// consecutive sorted points keep a compact cubic warp footprint.
__device__ __forceinline__ int bin_key(float px, float py, float pz) {
    int bx = (int)(px * 64.0f); bx = bx < 0 ? 0 : (bx > 63 ? 63 : bx);
    int by = (int)(py * 64.0f); by = by < 0 ? 0 : (by > 63 ? 63 : by);
    int bz = (int)(pz * 64.0f); bz = bz < 0 ? 0 : (bz > 63 ? 63 : bz);
    return (int)(part1by2((uint32_t)bx)
               | (part1by2((uint32_t)by) << 1)
               | (part1by2((uint32_t)bz) << 2));
}

__global__ void hist_kernel(const float* __restrict__ x) {
    int i = blockIdx.x * blockDim.x + threadIdx.x;
    if (i >= N_POINTS) return;
    float px = __ldg(&x[3 * i]), py = __ldg(&x[3 * i + 1]), pz = __ldg(&x[3 * i + 2]);
    atomicAdd(&g_hist[bin_key(px, py, pz)], 1u);
}

// Shuffle-based exclusive scan of 1024 bins per block; block offset claimed
// via atomic ticket (chunk permutation is harmless: within-chunk Morton order
// is preserved, and output is indexed by original point id).
__global__ void scan_kernel() {
    __shared__ unsigned int warp_sums[32];
    __shared__ unsigned int s_off;

    const int t     = threadIdx.x;
    const int lanei = t & 31;
    const int wid   = t >> 5;
    const int gid   = blockIdx.x * 1024 + t;

    const unsigned int c = g_hist[gid];

    unsigned int v = c;
#pragma unroll
    for (int off = 1; off < 32; off <<= 1) {
        unsigned int n = __shfl_up_sync(0xFFFFFFFFu, v, off);
        if (lanei >= off) v += n;
    }
    if (lanei == 31) warp_sums[wid] = v;
    __syncthreads();

    if (wid == 0) {
        unsigned int w = warp_sums[lanei];
        unsigned int wv = w;
#pragma unroll
        for (int off = 1; off < 32; off <<= 1) {
            unsigned int n = __shfl_up_sync(0xFFFFFFFFu, wv, off);
            if (lanei >= off) wv += n;
        }
        warp_sums[lanei] = wv - w;            // exclusive warp offset
        if (lanei == 31) s_off = atomicAdd(&g_hist[N_BINS], wv);  // block total
    }
    __syncthreads();

    g_hist[gid] = (v - c) + warp_sums[wid] + s_off;
}

__global__ void scatter_kernel(const float* __restrict__ x) {
    int i = blockIdx.x * blockDim.x + threadIdx.x;
    if (i >= N_POINTS) return;
    float px = __ldg(&x[3 * i]), py = __ldg(&x[3 * i + 1]), pz = __ldg(&x[3 * i + 2]);
    unsigned int r = atomicAdd(&g_hist[bin_key(px, py, pz)], 1u);
    g_xs4[r] = make_float4(px, py, pz, __int_as_float(i));
}

// Main: block = 512 threads = 16 warps, 64 points per block, 2 points per
// thread (MLP=16). Warp w handles level w. Reg-capped to 32 for 4 blocks/SM.
__global__ void __launch_bounds__(512, 4)
hash_embed_kernel(const float* __restrict__ tables,
                  float2* __restrict__ out,
                  Res16 R)
{
    __shared__ float2 s_out[64][17];   // [point][level], padded row
    __shared__ int    s_idx[64];

    const int warp = threadIdx.x >> 5;   // = level
    const int lane = threadIdx.x & 31;
    const int base = blockIdx.x * 64;

    const float4 pv0 = g_xs4[base + lane];
    const float4 pv1 = g_xs4[base + 32 + lane];
    if (warp == 0) {
        s_idx[lane]      = __float_as_int(pv0.w);
        s_idx[lane + 32] = __float_as_int(pv1.w);
    }

    const int level = warp;
    const float res  = R.r[level];
    const float grid = 2.0f / res;   // fp32, matches reference

    float px[2] = {pv0.x, pv1.x};
    float py[2] = {pv0.y, pv1.y};
    float pz[2] = {pv0.z, pv1.z};

    float wx[2], wy[2], wz[2];
    uint32_t h[2][8];

    // Phase 1: all ALU (cells, weights, hashes) for both points.
#pragma unroll
    for (int p = 0; p < 2; p++) {
        // bl = floor((x - BOX_MIN)/grid), BOX_MIN = -1. Bit-exact IEEE path.
        const float fx = (px[p] + 1.0f) / grid;
        const float fy = (py[p] + 1.0f) / grid;
        const float fz = (pz[p] + 1.0f) / grid;
        const float bxf = floorf(fx);
        const float byf = floorf(fy);
        const float bzf = floorf(fz);
        const int bx = (int)bxf;
        const int by = (int)byf;
        const int bz = (int)bzf;

        // Reference weight formulation (empirically fastest).
        const float vminx = bxf * grid - 1.0f;
        const float vminy = byf * grid - 1.0f;
        const float vminz = bzf * grid - 1.0f;
        wx[p] = (px[p] - vminx) / ((vminx + grid) - vminx);
        wy[p] = (py[p] - vminy) / ((vminy + grid) - vminy);
        wz[p] = (pz[p] - vminz) / ((vminz + grid) - vminz);

        const uint32_t hx0 = (uint32_t)bx;
        const uint32_t hx1 = (uint32_t)(bx + 1);
        const uint32_t hy0 = (uint32_t)by * PRIME_Y;
        const uint32_t hy1 = (uint32_t)(by + 1) * PRIME_Y;
        const uint32_t hz0 = (uint32_t)bz * PRIME_Z;
        const uint32_t hz1 = (uint32_t)(bz + 1) * PRIME_Z;

        h[p][0] = (hx0 ^ hy0 ^ hz0) & HASH_MASK;
        h[p][1] = (hx0 ^ hy0 ^ hz1) & HASH_MASK;
        h[p][2] = (hx0 ^ hy1 ^ hz0) & HASH_MASK;
        h[p][3] = (hx0 ^ hy1 ^ hz1) & HASH_MASK;
        h[p][4] = (hx1 ^ hy0 ^ hz0) & HASH_MASK;
        h[p][5] = (hx1 ^ hy0 ^ hz1) & HASH_MASK;
        h[p][6] = (hx1 ^ hy1 ^ hz0) & HASH_MASK;
        h[p][7] = (hx1 ^ hy1 ^ hz1) & HASH_MASK;
    }

    const float2* __restrict__ tab =
        (const float2*)tables + ((size_t)level << LOG2_HASHMAP_SIZE);

    // Phase 2: 16 independent gathers in flight.
    float2 v[2][8];
#pragma unroll
    for (int p = 0; p < 2; p++)
#pragma unroll
        for (int c = 0; c < 8; c++)
            v[p][c] = __ldg(&tab[h[p][c]]);

    // Phase 3: trilinear interpolation for both points.
#pragma unroll
    for (int p = 0; p < 2; p++) {
        const float owx = 1.0f - wx[p];
        const float owy = 1.0f - wy[p];
        const float owz = 1.0f - wz[p];

        float2 c00, c01, c10, c11;
        c00.x = v[p][0].x * owx + v[p][4].x * wx[p];
        c00.y = v[p][0].y * owx + v[p][4].y * wx[p];
        c01.x = v[p][1].x * owx + v[p][5].x * wx[p];
        c01.y = v[p][1].y * owx + v[p][5].y * wx[p];
        c10.x = v[p][2].x * owx + v[p][6].x * wx[p];
        c10.y = v[p][2].y * owx + v[p][6].y * wx[p];
        c11.x = v[p][3].x * owx + v[p][7].x * wx[p];
        c11.y = v[p][3].y * owx + v[p][7].y * wx[p];

        float2 c0, c1;
        c0.x = c00.x * owy + c10.x * wy[p];  c0.y = c00.y * owy + c10.y * wy[p];
        c1.x = c01.x * owy + c11.x * wy[p];  c1.y = c01.y * owy + c11.y * wy[p];

        float2 r2;
        r2.x = c0.x * owz + c1.x * wz[p];
        r2.y = c0.y * owz + c1.y * wz[p];

        s_out[p * 32 + lane][warp] = r2;
    }
    __syncthreads();

    // Coalesced writeback: 16 consecutive threads emit one point's 128B row.
    const int pt  = threadIdx.x >> 4;   // 0..31
    const int lev = threadIdx.x & 15;
    out[(size_t)s_idx[pt] * N_LEVELS + lev]      = s_out[pt][lev];
    out[(size_t)s_idx[pt + 32] * N_LEVELS + lev] = s_out[pt + 32][lev];
}

extern "C" void kernel_launch(void* const* d_in, const int* in_sizes, int n_in,
                              void* d_out, int out_size)
{
    const float* x      = (const float*)d_in[0];
    const float* tables = (const float*)d_in[1];
    float2* out         = (float2*)d_out;

    // Replicate numpy's RESOLUTIONS computation exactly (double libm, floor).
    Res16 R;
    const double b = exp((log(512.0) - log(16.0)) / 15.0);
    for (int i = 0; i < 16; i++) {
        R.r[i] = (float)floor(16.0 * pow(b, (double)i));
    }

    // Zero histogram + ticket counter in one capturable memset.
    void* hist_ptr = nullptr;
    cudaGetSymbolAddress(&hist_ptr, g_hist);
    cudaMemsetAsync(hist_ptr, 0, (N_BINS + 1) * sizeof(unsigned int));

    hist_kernel<<<N_POINTS / 256, 256>>>(x);
    scan_kernel<<<256, 1024>>>();
    scatter_kernel<<<N_POINTS / 256, 256>>>(x);
    hash_embed_kernel<<<N_POINTS / 64, 512>>>(tables, out, R);
}

// round 14
// speedup vs baseline: 1.0589x; 1.0589x over previous
#include <cuda_runtime.h>
#include <math.h>
#include <stdint.h>

#define N_LEVELS 16
#define LOG2_HASHMAP_SIZE 19
#define HASH_MASK ((1u << LOG2_HASHMAP_SIZE) - 1u)
#define N_POINTS 1048576
#define PRIME_Y 2654435761u
#define PRIME_Z 805459861u
#define N_BINS 262144         // 64^3 spatial bins, Morton-ordered

struct Res16 { float r[16]; };

// Scratch (no cudaMalloc allowed)
__device__ float4       g_xs4[N_POINTS];      // sorted points + orig idx in .w
__device__ unsigned int g_hist[N_BINS + 1];   // counts->offsets; [N_BINS] = ticket

__device__ __forceinline__ uint32_t part1by2(uint32_t v) {
    v &= 0x3FFu;
    v = (v * 0x00010001u) & 0xFF0000FFu;
    v = (v * 0x00000101u) & 0x0F00F00Fu;
    v = (v * 0x00000011u) & 0xC30C30C3u;
    v = (v * 0x00000005u) & 0x49249249u;
    return v;
}

// Morton key over 64^3: consecutive bins tile space as nested cubes, so 32
// consecutive sorted points keep a compact cubic warp footprint.
__device__ __forceinline__ int bin_key(float px, float py, float pz) {
    int bx = (int)(px * 64.0f); bx = bx < 0 ? 0 : (bx > 63 ? 63 : bx);
    int by = (int)(py * 64.0f); by = by < 0 ? 0 : (by > 63 ? 63 : by);
    int bz = (int)(pz * 64.0f); bz = bz < 0 ? 0 : (bz > 63 ? 63 : bz);
    return (int)(part1by2((uint32_t)bx)
               | (part1by2((uint32_t)by) << 1)
               | (part1by2((uint32_t)bz) << 2));
}

// 4 points per thread via three aligned float4 loads (48B), 4 independent
// atomic chains per thread (ILP to hide L2 atomic latency).
__global__ void hist_kernel(const float4* __restrict__ x4) {
    int t = blockIdx.x * blockDim.x + threadIdx.x;
    if (t >= N_POINTS / 4) return;
    const float4 a = __ldg(&x4[3 * t + 0]);
    const float4 b = __ldg(&x4[3 * t + 1]);
    const float4 c = __ldg(&x4[3 * t + 2]);
    const int k0 = bin_key(a.x, a.y, a.z);
    const int k1 = bin_key(a.w, b.x, b.y);
    const int k2 = bin_key(b.z, b.w, c.x);
    const int k3 = bin_key(c.y, c.z, c.w);
    atomicAdd(&g_hist[k0], 1u);
    atomicAdd(&g_hist[k1], 1u);
    atomicAdd(&g_hist[k2], 1u);
    atomicAdd(&g_hist[k3], 1u);
}

// Shuffle-based exclusive scan of 1024 bins per block; block offset claimed
// via atomic ticket (chunk permutation is harmless: within-chunk Morton order
// is preserved, and output is indexed by original point id).
__global__ void scan_kernel() {
    __shared__ unsigned int warp_sums[32];
    __shared__ unsigned int s_off;

    const int t     = threadIdx.x;
    const int lanei = t & 31;
    const int wid   = t >> 5;
    const int gid   = blockIdx.x * 1024 + t;

    const unsigned int c = g_hist[gid];

    unsigned int v = c;
#pragma unroll
    for (int off = 1; off < 32; off <<= 1) {
        unsigned int n = __shfl_up_sync(0xFFFFFFFFu, v, off);
        if (lanei >= off) v += n;
    }
    if (lanei == 31) warp_sums[wid] = v;
    __syncthreads();

    if (wid == 0) {
        unsigned int w = warp_sums[lanei];
        unsigned int wv = w;
#pragma unroll
        for (int off = 1; off < 32; off <<= 1) {
            unsigned int n = __shfl_up_sync(0xFFFFFFFFu, wv, off);
            if (lanei >= off) wv += n;
        }
        warp_sums[lanei] = wv - w;            // exclusive warp offset
        if (lanei == 31) s_off = atomicAdd(&g_hist[N_BINS], wv);  // block total
    }
    __syncthreads();

    g_hist[gid] = (v - c) + warp_sums[wid] + s_off;
}

// 4 points per thread, same float4 pattern; 4 independent atomic+store chains.
__global__ void scatter_kernel(const float4* __restrict__ x4) {
    int t = blockIdx.x * blockDim.x + threadIdx.x;
    if (t >= N_POINTS / 4) return;
    const float4 a = __ldg(&x4[3 * t + 0]);
    const float4 b = __ldg(&x4[3 * t + 1]);
    const float4 c = __ldg(&x4[3 * t + 2]);
    const int i0 = 4 * t;

    const int k0 = bin_key(a.x, a.y, a.z);
    const int k1 = bin_key(a.w, b.x, b.y);
    const int k2 = bin_key(b.z, b.w, c.x);
    const int k3 = bin_key(c.y, c.z, c.w);

    const unsigned int r0 = atomicAdd(&g_hist[k0], 1u);
    const unsigned int r1 = atomicAdd(&g_hist[k1], 1u);
    const unsigned int r2 = atomicAdd(&g_hist[k2], 1u);
    const unsigned int r3 = atomicAdd(&g_hist[k3], 1u);

    g_xs4[r0] = make_float4(a.x, a.y, a.z, __int_as_float(i0 + 0));
    g_xs4[r1] = make_float4(a.w, b.x, b.y, __int_as_float(i0 + 1));
    g_xs4[r2] = make_float4(b.z, b.w, c.x, __int_as_float(i0 + 2));
    g_xs4[r3] = make_float4(c.y, c.z, c.w, __int_as_float(i0 + 3));
}

// Main: block = 512 threads = 16 warps, 64 points per block, 2 points per
// thread (MLP=16). Warp w handles level w. PROTECTED round-12 body: natural
// 40-reg compile (no min-blocks cap — R13 proved the cap hurts ILP).
__global__ void __launch_bounds__(512)
hash_embed_kernel(const float* __restrict__ tables,
                  float2* __restrict__ out,
                  Res16 R)
{
    __shared__ float2 s_out[64][17];   // [point][level], padded row
    __shared__ int    s_idx[64];

    const int warp = threadIdx.x >> 5;   // = level
    const int lane = threadIdx.x & 31;
    const int base = blockIdx.x * 64;

    const float4 pv0 = g_xs4[base + lane];
    const float4 pv1 = g_xs4[base + 32 + lane];
    if (warp == 0) {
        s_idx[lane]      = __float_as_int(pv0.w);
        s_idx[lane + 32] = __float_as_int(pv1.w);
    }

    const int level = warp;
    const float res  = R.r[level];
    const float grid = 2.0f / res;   // fp32, matches reference

    float px[2] = {pv0.x, pv1.x};
    float py[2] = {pv0.y, pv1.y};
    float pz[2] = {pv0.z, pv1.z};

    float wx[2], wy[2], wz[2];
    uint32_t h[2][8];

    // Phase 1: all ALU (cells, weights, hashes) for both points.
#pragma unroll
    for (int p = 0; p < 2; p++) {
        // bl = floor((x - BOX_MIN)/grid), BOX_MIN = -1. Bit-exact IEEE path.
        const float fx = (px[p] + 1.0f) / grid;
        const float fy = (py[p] + 1.0f) / grid;
        const float fz = (pz[p] + 1.0f) / grid;
        const float bxf = floorf(fx);
        const float byf = floorf(fy);
        const float bzf = floorf(fz);
        const int bx = (int)bxf;
        const int by = (int)byf;
        const int bz = (int)bzf;

        // Reference weight formulation (empirically fastest).
        const float vminx = bxf * grid - 1.0f;
        const float vminy = byf * grid - 1.0f;
        const float vminz = bzf * grid - 1.0f;
        wx[p] = (px[p] - vminx) / ((vminx + grid) - vminx);
        wy[p] = (py[p] - vminy) / ((vminy + grid) - vminy);
        wz[p] = (pz[p] - vminz) / ((vminz + grid) - vminz);

        const uint32_t hx0 = (uint32_t)bx;
        const uint32_t hx1 = (uint32_t)(bx + 1);
        const uint32_t hy0 = (uint32_t)by * PRIME_Y;
        const uint32_t hy1 = (uint32_t)(by + 1) * PRIME_Y;
        const uint32_t hz0 = (uint32_t)bz * PRIME_Z;
        const uint32_t hz1 = (uint32_t)(bz + 1) * PRIME_Z;

        h[p][0] = (hx0 ^ hy0 ^ hz0) & HASH_MASK;
        h[p][1] = (hx0 ^ hy0 ^ hz1) & HASH_MASK;
        h[p][2] = (hx0 ^ hy1 ^ hz0) & HASH_MASK;
        h[p][3] = (hx0 ^ hy1 ^ hz1) & HASH_MASK;
        h[p][4] = (hx1 ^ hy0 ^ hz0) & HASH_MASK;
        h[p][5] = (hx1 ^ hy0 ^ hz1) & HASH_MASK;
        h[p][6] = (hx1 ^ hy1 ^ hz0) & HASH_MASK;
        h[p][7] = (hx1 ^ hy1 ^ hz1) & HASH_MASK;
    }

    const float2* __restrict__ tab =
        (const float2*)tables + ((size_t)level << LOG2_HASHMAP_SIZE);

    // Phase 2: 16 independent gathers in flight.
    float2 v[2][8];
#pragma unroll
    for (int p = 0; p < 2; p++)
#pragma unroll
        for (int c = 0; c < 8; c++)
            v[p][c] = __ldg(&tab[h[p][c]]);

    // Phase 3: trilinear interpolation for both points.
#pragma unroll
    for (int p = 0; p < 2; p++) {
        const float owx = 1.0f - wx[p];
        const float owy = 1.0f - wy[p];
        const float owz = 1.0f - wz[p];

        float2 c00, c01, c10, c11;
        c00.x = v[p][0].x * owx + v[p][4].x * wx[p];
        c00.y = v[p][0].y * owx + v[p][4].y * wx[p];
        c01.x = v[p][1].x * owx + v[p][5].x * wx[p];
        c01.y = v[p][1].y * owx + v[p][5].y * wx[p];
        c10.x = v[p][2].x * owx + v[p][6].x * wx[p];
        c10.y = v[p][2].y * owx + v[p][6].y * wx[p];
        c11.x = v[p][3].x * owx + v[p][7].x * wx[p];
        c11.y = v[p][3].y * owx + v[p][7].y * wx[p];

        float2 c0, c1;
        c0.x = c00.x * owy + c10.x * wy[p];  c0.y = c00.y * owy + c10.y * wy[p];
        c1.x = c01.x * owy + c11.x * wy[p];  c1.y = c01.y * owy + c11.y * wy[p];

        float2 r2;
        r2.x = c0.x * owz + c1.x * wz[p];
        r2.y = c0.y * owz + c1.y * wz[p];

        s_out[p * 32 + lane][warp] = r2;
    }
    __syncthreads();

    // Coalesced writeback: 16 consecutive threads emit one point's 128B row.
    const int pt  = threadIdx.x >> 4;   // 0..31
    const int lev = threadIdx.x & 15;
    out[(size_t)s_idx[pt] * N_LEVELS + lev]      = s_out[pt][lev];
    out[(size_t)s_idx[pt + 32] * N_LEVELS + lev] = s_out[pt + 32][lev];
}

extern "C" void kernel_launch(void* const* d_in, const int* in_sizes, int n_in,
                              void* d_out, int out_size)
{
    const float* x      = (const float*)d_in[0];
    const float* tables = (const float*)d_in[1];
    float2* out         = (float2*)d_out;

    // Replicate numpy's RESOLUTIONS computation exactly (double libm, floor).
    Res16 R;
    const double b = exp((log(512.0) - log(16.0)) / 15.0);
    for (int i = 0; i < 16; i++) {
        R.r[i] = (float)floor(16.0 * pow(b, (double)i));
    }

    // Zero histogram + ticket counter in one capturable memset.
    void* hist_ptr = nullptr;
    cudaGetSymbolAddress(&hist_ptr, g_hist);
    cudaMemsetAsync(hist_ptr, 0, (N_BINS + 1) * sizeof(unsigned int));

    hist_kernel<<<(N_POINTS / 4) / 256, 256>>>((const float4*)x);
    scan_kernel<<<256, 1024>>>();
    scatter_kernel<<<(N_POINTS / 4) / 256, 256>>>((const float4*)x);
    hash_embed_kernel<<<N_POINTS / 64, 512>>>(tables, out, R);
}

// round 15
// speedup vs baseline: 1.0720x; 1.0124x over previous
#include <cuda_runtime.h>
#include <math.h>
#include <stdint.h>

#define N_LEVELS 16
#define LOG2_HASHMAP_SIZE 19
#define HASH_MASK ((1u << LOG2_HASHMAP_SIZE) - 1u)
#define N_POINTS 1048576
#define PRIME_Y 2654435761u
#define PRIME_Z 805459861u
#define N_BINS 262144         // 64^3 spatial bins, Morton-ordered

struct Res16 { float r[16]; };

// Scratch (no cudaMalloc allowed)
__device__ float4       g_xs4[N_POINTS];      // sorted points + orig idx in .w
__device__ unsigned int g_hist[N_BINS + 1];   // counts->offsets; [N_BINS] = ticket

__device__ __forceinline__ uint32_t part1by2(uint32_t v) {
    v &= 0x3FFu;
    v = (v * 0x00010001u) & 0xFF0000FFu;
    v = (v * 0x00000101u) & 0x0F00F00Fu;
    v = (v * 0x00000011u) & 0xC30C30C3u;
    v = (v * 0x00000005u) & 0x49249249u;
    return v;
}

// Morton key over 64^3: consecutive bins tile space as nested cubes, so 32
// consecutive sorted points keep a compact cubic warp footprint.
__device__ __forceinline__ int bin_key(float px, float py, float pz) {
    int bx = (int)(px * 64.0f); bx = bx < 0 ? 0 : (bx > 63 ? 63 : bx);
    int by = (int)(py * 64.0f); by = by < 0 ? 0 : (by > 63 ? 63 : by);
    int bz = (int)(pz * 64.0f); bz = bz < 0 ? 0 : (bz > 63 ? 63 : bz);
    return (int)(part1by2((uint32_t)bx)
               | (part1by2((uint32_t)by) << 1)
               | (part1by2((uint32_t)bz) << 2));
}

__global__ void hist_kernel(const float* __restrict__ x) {
    int i = blockIdx.x * blockDim.x + threadIdx.x;
    if (i >= N_POINTS) return;
    float px = __ldg(&x[3 * i]), py = __ldg(&x[3 * i + 1]), pz = __ldg(&x[3 * i + 2]);
    atomicAdd(&g_hist[bin_key(px, py, pz)], 1u);
}

// Shuffle-based exclusive scan of 1024 bins per block; block offset claimed
// via atomic ticket (chunk permutation is harmless: within-chunk Morton order
// is preserved, and output is indexed by original point id).
__global__ void scan_kernel() {
    __shared__ unsigned int warp_sums[32];
    __shared__ unsigned int s_off;

    const int t     = threadIdx.x;
    const int lanei = t & 31;
    const int wid   = t >> 5;
    const int gid   = blockIdx.x * 1024 + t;

    const unsigned int c = g_hist[gid];

    unsigned int v = c;
#pragma unroll
    for (int off = 1; off < 32; off <<= 1) {
        unsigned int n = __shfl_up_sync(0xFFFFFFFFu, v, off);
        if (lanei >= off) v += n;
    }
    if (lanei == 31) warp_sums[wid] = v;
    __syncthreads();

    if (wid == 0) {
        unsigned int w = warp_sums[lanei];
        unsigned int wv = w;
#pragma unroll
        for (int off = 1; off < 32; off <<= 1) {
            unsigned int n = __shfl_up_sync(0xFFFFFFFFu, wv, off);
            if (lanei >= off) wv += n;
        }
        warp_sums[lanei] = wv - w;            // exclusive warp offset
        if (lanei == 31) s_off = atomicAdd(&g_hist[N_BINS], wv);  // block total
    }
    __syncthreads();

    g_hist[gid] = (v - c) + warp_sums[wid] + s_off;
}

__global__ void scatter_kernel(const float* __restrict__ x) {
    int i = blockIdx.x * blockDim.x + threadIdx.x;
    if (i >= N_POINTS) return;
    float px = __ldg(&x[3 * i]), py = __ldg(&x[3 * i + 1]), pz = __ldg(&x[3 * i + 2]);
    unsigned int r = atomicAdd(&g_hist[bin_key(px, py, pz)], 1u);
    g_xs4[r] = make_float4(px, py, pz, __int_as_float(i));
}

__device__ __forceinline__ void st_cs_f2(float2* p, float2 v) {
    asm volatile("st.global.cs.v2.f32 [%0], {%1, %2};"
                 :: "l"(p), "f"(v.x), "f"(v.y) : "memory");
}

// Main: block = 512 threads = 16 warps, 64 points per block, 2 points per
// thread (MLP=16). Warp w handles level w. Gather path PROTECTED (R12 body);
// the ONLY change vs R12: output stores use .cs (write-once stream, keep it
// from evicting the 64MB table working set out of L2).
__global__ void __launch_bounds__(512)
hash_embed_kernel(const float* __restrict__ tables,
                  float2* __restrict__ out,
                  Res16 R)
{
    __shared__ float2 s_out[64][17];   // [point][level], padded row
    __shared__ int    s_idx[64];

    const int warp = threadIdx.x >> 5;   // = level
    const int lane = threadIdx.x & 31;
    const int base = blockIdx.x * 64;

    const float4 pv0 = g_xs4[base + lane];
    const float4 pv1 = g_xs4[base + 32 + lane];
    if (warp == 0) {
        s_idx[lane]      = __float_as_int(pv0.w);
        s_idx[lane + 32] = __float_as_int(pv1.w);
    }

    const int level = warp;
    const float res  = R.r[level];
    const float grid = 2.0f / res;   // fp32, matches reference

    float px[2] = {pv0.x, pv1.x};
    float py[2] = {pv0.y, pv1.y};
    float pz[2] = {pv0.z, pv1.z};

    float wx[2], wy[2], wz[2];
    uint32_t h[2][8];

    // Phase 1: all ALU (cells, weights, hashes) for both points.
#pragma unroll
    for (int p = 0; p < 2; p++) {
        // bl = floor((x - BOX_MIN)/grid), BOX_MIN = -1. Bit-exact IEEE path.
        const float fx = (px[p] + 1.0f) / grid;
        const float fy = (py[p] + 1.0f) / grid;
        const float fz = (pz[p] + 1.0f) / grid;
        const float bxf = floorf(fx);
        const float byf = floorf(fy);
        const float bzf = floorf(fz);
        const int bx = (int)bxf;
        const int by = (int)byf;
        const int bz = (int)bzf;

        // Reference weight formulation (empirically fastest).
        const float vminx = bxf * grid - 1.0f;
        const float vminy = byf * grid - 1.0f;
        const float vminz = bzf * grid - 1.0f;
        wx[p] = (px[p] - vminx) / ((vminx + grid) - vminx);
        wy[p] = (py[p] - vminy) / ((vminy + grid) - vminy);
        wz[p] = (pz[p] - vminz) / ((vminz + grid) - vminz);

        const uint32_t hx0 = (uint32_t)bx;
        const uint32_t hx1 = (uint32_t)(bx + 1);
        const uint32_t hy0 = (uint32_t)by * PRIME_Y;
        const uint32_t hy1 = (uint32_t)(by + 1) * PRIME_Y;
        const uint32_t hz0 = (uint32_t)bz * PRIME_Z;
        const uint32_t hz1 = (uint32_t)(bz + 1) * PRIME_Z;

        h[p][0] = (hx0 ^ hy0 ^ hz0) & HASH_MASK;
        h[p][1] = (hx0 ^ hy0 ^ hz1) & HASH_MASK;
        h[p][2] = (hx0 ^ hy1 ^ hz0) & HASH_MASK;
        h[p][3] = (hx0 ^ hy1 ^ hz1) & HASH_MASK;
        h[p][4] = (hx1 ^ hy0 ^ hz0) & HASH_MASK;
        h[p][5] = (hx1 ^ hy0 ^ hz1) & HASH_MASK;
        h[p][6] = (hx1 ^ hy1 ^ hz0) & HASH_MASK;
        h[p][7] = (hx1 ^ hy1 ^ hz1) & HASH_MASK;
    }

    const float2* __restrict__ tab =
        (const float2*)tables + ((size_t)level << LOG2_HASHMAP_SIZE);

    // Phase 2: 16 independent gathers in flight.
    float2 v[2][8];
#pragma unroll
    for (int p = 0; p < 2; p++)
#pragma unroll
        for (int c = 0; c < 8; c++)
            v[p][c] = __ldg(&tab[h[p][c]]);

    // Phase 3: trilinear interpolation for both points.
#pragma unroll
    for (int p = 0; p < 2; p++) {
        const float owx = 1.0f - wx[p];
        const float owy = 1.0f - wy[p];
        const float owz = 1.0f - wz[p];

        float2 c00, c01, c10, c11;
        c00.x = v[p][0].x * owx + v[p][4].x * wx[p];
        c00.y = v[p][0].y * owx + v[p][4].y * wx[p];
        c01.x = v[p][1].x * owx + v[p][5].x * wx[p];
        c01.y = v[p][1].y * owx + v[p][5].y * wx[p];
        c10.x = v[p][2].x * owx + v[p][6].x * wx[p];
        c10.y = v[p][2].y * owx + v[p][6].y * wx[p];
        c11.x = v[p][3].x * owx + v[p][7].x * wx[p];
        c11.y = v[p][3].y * owx + v[p][7].y * wx[p];

        float2 c0, c1;
        c0.x = c00.x * owy + c10.x * wy[p];  c0.y = c00.y * owy + c10.y * wy[p];
        c1.x = c01.x * owy + c11.x * wy[p];  c1.y = c01.y * owy + c11.y * wy[p];

        float2 r2;
        r2.x = c0.x * owz + c1.x * wz[p];
        r2.y = c0.y * owz + c1.y * wz[p];

        s_out[p * 32 + lane][warp] = r2;
    }
    __syncthreads();

    // Coalesced writeback: 16 consecutive threads emit one point's 128B row.
    // .cs: write-once stream; evict-first in L2 to protect table residency.
    const int pt  = threadIdx.x >> 4;   // 0..31
    const int lev = threadIdx.x & 15;
    st_cs_f2(&out[(size_t)s_idx[pt] * N_LEVELS + lev],      s_out[pt][lev]);
    st_cs_f2(&out[(size_t)s_idx[pt + 32] * N_LEVELS + lev], s_out[pt + 32][lev]);
}

extern "C" void kernel_launch(void* const* d_in, const int* in_sizes, int n_in,
                              void* d_out, int out_size)
{
    const float* x      = (const float*)d_in[0];
    const float* tables = (const float*)d_in[1];
    float2* out         = (float2*)d_out;

    // Replicate numpy's RESOLUTIONS computation exactly (double libm, floor).
    Res16 R;
    const double b = exp((log(512.0) - log(16.0)) / 15.0);
    for (int i = 0; i < 16; i++) {
        R.r[i] = (float)floor(16.0 * pow(b, (double)i));
    }

    // Zero histogram + ticket counter in one capturable memset.
    void* hist_ptr = nullptr;
    cudaGetSymbolAddress(&hist_ptr, g_hist);
    cudaMemsetAsync(hist_ptr, 0, (N_BINS + 1) * sizeof(unsigned int));

    hist_kernel<<<N_POINTS / 256, 256>>>(x);
    scan_kernel<<<256, 1024>>>();
    scatter_kernel<<<N_POINTS / 256, 256>>>(x);
    hash_embed_kernel<<<N_POINTS / 64, 512>>>(tables, out, R);
}

// round 16
// speedup vs baseline: 1.1169x; 1.0419x over previous
#include <cuda_runtime.h>
#include <math.h>
#include <stdint.h>

#define N_LEVELS 16
#define LOG2_HASHMAP_SIZE 19
#define HASH_MASK ((1u << LOG2_HASHMAP_SIZE) - 1u)
#define N_POINTS 1048576
#define PRIME_Y 2654435761u
#define PRIME_Z 805459861u
#define N_BINS 262144         // 64^3 spatial bins, Morton-ordered

struct Res16 { float r[16]; };

// Scratch (no cudaMalloc allowed)
__device__ float4       g_xs4[N_POINTS];      // sorted points + orig idx in .w
__device__ unsigned int g_hist[N_BINS + 1];   // counts->offsets; [N_BINS] = ticket

__device__ __forceinline__ uint32_t part1by2(uint32_t v) {
    v &= 0x3FFu;
    v = (v * 0x00010001u) & 0xFF0000FFu;
    v = (v * 0x00000101u) & 0x0F00F00Fu;
    v = (v * 0x00000011u) & 0xC30C30C3u;
    v = (v * 0x00000005u) & 0x49249249u;
    return v;
}

// Morton key over 64^3: consecutive bins tile space as nested cubes, so 32
// consecutive sorted points keep a compact cubic warp footprint.
__device__ __forceinline__ int bin_key(float px, float py, float pz) {
    int bx = (int)(px * 64.0f); bx = bx < 0 ? 0 : (bx > 63 ? 63 : bx);
    int by = (int)(py * 64.0f); by = by < 0 ? 0 : (by > 63 ? 31 + 32 : by);
    by = by > 63 ? 63 : by;
    int bz = (int)(pz * 64.0f); bz = bz < 0 ? 0 : (bz > 63 ? 63 : bz);
    return (int)(part1by2((uint32_t)bx)
               | (part1by2((uint32_t)by) << 1)
               | (part1by2((uint32_t)bz) << 2));
}

__global__ void hist_kernel(const float* __restrict__ x) {
    int i = blockIdx.x * blockDim.x + threadIdx.x;
    if (i >= N_POINTS) return;
    float px = __ldg(&x[3 * i]), py = __ldg(&x[3 * i + 1]), pz = __ldg(&x[3 * i + 2]);
    atomicAdd(&g_hist[bin_key(px, py, pz)], 1u);
}

// Shuffle-based exclusive scan of 1024 bins per block; block offset claimed
// via atomic ticket (chunk permutation is harmless: within-chunk Morton order
// is preserved, and output is indexed by original point id).
__global__ void scan_kernel() {
    __shared__ unsigned int warp_sums[32];
    __shared__ unsigned int s_off;

    const int t     = threadIdx.x;
    const int lanei = t & 31;
    const int wid   = t >> 5;
    const int gid   = blockIdx.x * 1024 + t;

    const unsigned int c = g_hist[gid];

    unsigned int v = c;
#pragma unroll
    for (int off = 1; off < 32; off <<= 1) {
        unsigned int n = __shfl_up_sync(0xFFFFFFFFu, v, off);
        if (lanei >= off) v += n;
    }
    if (lanei == 31) warp_sums[wid] = v;
    __syncthreads();

    if (wid == 0) {
        unsigned int w = warp_sums[lanei];
        unsigned int wv = w;
#pragma unroll
        for (int off = 1; off < 32; off <<= 1) {
            unsigned int n = __shfl_up_sync(0xFFFFFFFFu, wv, off);
            if (lanei >= off) wv += n;
        }
        warp_sums[lanei] = wv - w;            // exclusive warp offset
        if (lanei == 31) s_off = atomicAdd(&g_hist[N_BINS], wv);  // block total
    }
    __syncthreads();

    g_hist[gid] = (v - c) + warp_sums[wid] + s_off;
}

__global__ void scatter_kernel(const float* __restrict__ x) {
    int i = blockIdx.x * blockDim.x + threadIdx.x;
    if (i >= N_POINTS) return;
    float px = __ldg(&x[3 * i]), py = __ldg(&x[3 * i + 1]), pz = __ldg(&x[3 * i + 2]);
    unsigned int r = atomicAdd(&g_hist[bin_key(px, py, pz)], 1u);
    g_xs4[r] = make_float4(px, py, pz, __int_as_float(i));
}

__device__ __forceinline__ void st_cs_f2(float2* p, float2 v) {
    asm volatile("st.global.cs.v2.f32 [%0], {%1, %2};"
                 :: "l"(p), "f"(v.x), "f"(v.y) : "memory");
}

// Main: block = 512 threads = 16 warps, 64 points per block, 2 points per
// thread (MLP=16). LOAD-BALANCED level mapping: warp w handles point A at
// level w and point B at level 15-w, so every warp's wavefront cost is
// ~wf(w)+wf(15-w) (max ~136) instead of 2*wf(w) (max ~256) — the res-512
// straggler warp no longer serializes the block barrier.
__global__ void __launch_bounds__(512)
hash_embed_kernel(const float* __restrict__ tables,
                  float2* __restrict__ out,
                  Res16 R)
{
    __shared__ float2 s_out[64][17];   // [point][level], padded row
    __shared__ int    s_idx[64];

    const int warp = threadIdx.x >> 5;
    const int lane = threadIdx.x & 31;
    const int base = blockIdx.x * 64;

    const float4 pv0 = g_xs4[base + lane];
    const float4 pv1 = g_xs4[base + 32 + lane];
    if (warp == 0) {
        s_idx[lane]      = __float_as_int(pv0.w);
        s_idx[lane + 32] = __float_as_int(pv1.w);
    }

    const int levA = warp;          // point 0's level
    const int levB = 15 - warp;     // point 1's level (complementary cost)
    const int lev[2] = {levA, levB};

    float px[2] = {pv0.x, pv1.x};
    float py[2] = {pv0.y, pv1.y};
    float pz[2] = {pv0.z, pv1.z};

    float wx[2], wy[2], wz[2];
    uint32_t h[2][8];

    // Phase 1: all ALU (cells, weights, hashes) for both points.
#pragma unroll
    for (int p = 0; p < 2; p++) {
        const float res  = R.r[lev[p]];
        const float grid = 2.0f / res;   // fp32, matches reference

        // bl = floor((x - BOX_MIN)/grid), BOX_MIN = -1. Bit-exact IEEE path.
        const float fx = (px[p] + 1.0f) / grid;
        const float fy = (py[p] + 1.0f) / grid;
        const float fz = (pz[p] + 1.0f) / grid;
        const float bxf = floorf(fx);
        const float byf = floorf(fy);
        const float bzf = floorf(fz);
        const int bx = (int)bxf;
        const int by = (int)byf;
        const int bz = (int)bzf;

        // Reference weight formulation (empirically fastest).
        const float vminx = bxf * grid - 1.0f;
        const float vminy = byf * grid - 1.0f;
        const float vminz = bzf * grid - 1.0f;
        wx[p] = (px[p] - vminx) / ((vminx + grid) - vminx);
        wy[p] = (py[p] - vminy) / ((vminy + grid) - vminy);
        wz[p] = (pz[p] - vminz) / ((vminz + grid) - vminz);

        const uint32_t hx0 = (uint32_t)bx;
        const uint32_t hx1 = (uint32_t)(bx + 1);
        const uint32_t hy0 = (uint32_t)by * PRIME_Y;
        const uint32_t hy1 = (uint32_t)(by + 1) * PRIME_Y;
        const uint32_t hz0 = (uint32_t)bz * PRIME_Z;
        const uint32_t hz1 = (uint32_t)(bz + 1) * PRIME_Z;

        h[p][0] = (hx0 ^ hy0 ^ hz0) & HASH_MASK;
        h[p][1] = (hx0 ^ hy0 ^ hz1) & HASH_MASK;
        h[p][2] = (hx0 ^ hy1 ^ hz0) & HASH_MASK;
        h[p][3] = (hx0 ^ hy1 ^ hz1) & HASH_MASK;
        h[p][4] = (hx1 ^ hy0 ^ hz0) & HASH_MASK;
        h[p][5] = (hx1 ^ hy0 ^ hz1) & HASH_MASK;
        h[p][6] = (hx1 ^ hy1 ^ hz0) & HASH_MASK;
        h[p][7] = (hx1 ^ hy1 ^ hz1) & HASH_MASK;
    }

    const float2* __restrict__ tabA =
        (const float2*)tables + ((size_t)levA << LOG2_HASHMAP_SIZE);
    const float2* __restrict__ tabB =
        (const float2*)tables + ((size_t)levB << LOG2_HASHMAP_SIZE);

    // Phase 2: 16 independent gathers in flight.
    float2 v[2][8];
#pragma unroll
    for (int c = 0; c < 8; c++) v[0][c] = __ldg(&tabA[h[0][c]]);
#pragma unroll
    for (int c = 0; c < 8; c++) v[1][c] = __ldg(&tabB[h[1][c]]);

    // Phase 3: trilinear interpolation for both points.
#pragma unroll
    for (int p = 0; p < 2; p++) {
        const float owx = 1.0f - wx[p];
        const float owy = 1.0f - wy[p];
        const float owz = 1.0f - wz[p];

        float2 c00, c01, c10, c11;
        c00.x = v[p][0].x * owx + v[p][4].x * wx[p];
        c00.y = v[p][0].y * owx + v[p][4].y * wx[p];
        c01.x = v[p][1].x * owx + v[p][5].x * wx[p];
        c01.y = v[p][1].y * owx + v[p][5].y * wx[p];
        c10.x = v[p][2].x * owx + v[p][6].x * wx[p];
        c10.y = v[p][2].y * owx + v[p][6].y * wx[p];
        c11.x = v[p][3].x * owx + v[p][7].x * wx[p];
        c11.y = v[p][3].y * owx + v[p][7].y * wx[p];

        float2 c0, c1;
        c0.x = c00.x * owy + c10.x * wy[p];  c0.y = c00.y * owy + c10.y * wy[p];
        c1.x = c01.x * owy + c11.x * wy[p];  c1.y = c01.y * owy + c11.y * wy[p];

        float2 r2;
        r2.x = c0.x * owz + c1.x * wz[p];
        r2.y = c0.y * owz + c1.y * wz[p];

        s_out[p * 32 + lane][lev[p]] = r2;
    }
    __syncthreads();

    // Coalesced writeback: 16 consecutive threads emit one point's 128B row.
    // .cs: write-once stream; evict-first in L2 to protect table residency.
    const int pt  = threadIdx.x >> 4;   // 0..31
    const int levw = threadIdx.x & 15;
    st_cs_f2(&out[(size_t)s_idx[pt] * N_LEVELS + levw],      s_out[pt][levw]);
    st_cs_f2(&out[(size_t)s_idx[pt + 32] * N_LEVELS + levw], s_out[pt + 32][levw]);
}

extern "C" void kernel_launch(void* const* d_in, const int* in_sizes, int n_in,
                              void* d_out, int out_size)
{
    const float* x      = (const float*)d_in[0];
    const float* tables = (const float*)d_in[1];
    float2* out         = (float2*)d_out;

    // Replicate numpy's RESOLUTIONS computation exactly (double libm, floor).
    Res16 R;
    const double b = exp((log(512.0) - log(16.0)) / 15.0);
    for (int i = 0; i < 16; i++) {
        R.r[i] = (float)floor(16.0 * pow(b, (double)i));
    }

    // Zero histogram + ticket counter in one capturable memset.
    void* hist_ptr = nullptr;
    cudaGetSymbolAddress(&hist_ptr, g_hist);
    cudaMemsetAsync(hist_ptr, 0, (N_BINS + 1) * sizeof(unsigned int));

    hist_kernel<<<N_POINTS / 256, 256>>>(x);
    scan_kernel<<<256, 1024>>>();
    scatter_kernel<<<N_POINTS / 256, 256>>>(x);
    hash_embed_kernel<<<N_POINTS / 64, 512>>>(tables, out, R);
}